// round 3
// baseline (speedup 1.0000x reference)
#include <cuda_runtime.h>
#include <cuda_bf16.h>

// ---------------------------------------------------------------------------
// GCN_33114197852819 : 4-layer GCN, B=65536, N=12, feats 256->512->256->128->40
// Round 2: fused fp32 baseline using packed fma.rn.f32x2.
// Fix vs R1: A-table SMEM load used 288 threads with blockDim=256, leaving
// Ash[256..287] and Ash[544..575] (tails of A2/A4) as garbage.
// ---------------------------------------------------------------------------

#define NB_TOTAL 65536
#define NNODE 12

// Precomputed per-layer mixing matrices A_l = att_l * (adj + softmax(relu(nv1@nv2)))
__device__ float g_A[4 * 144];

__global__ void precompute_kernel(const float* __restrict__ adj,
                                  const float* __restrict__ nv1,
                                  const float* __restrict__ nv2,
                                  const float* __restrict__ a1,
                                  const float* __restrict__ a2,
                                  const float* __restrict__ a3,
                                  const float* __restrict__ a4)
{
    int n = threadIdx.x;
    if (n >= 12) return;
    float r[12];
    float mx = -1e30f;
    for (int m = 0; m < 12; m++) {
        float s = 0.f;
        for (int k = 0; k < 10; k++) s += nv1[n * 10 + k] * nv2[k * 12 + m];
        s = fmaxf(s, 0.f);
        r[m] = s;
        mx = fmaxf(mx, s);
    }
    float den = 0.f;
    for (int m = 0; m < 12; m++) { r[m] = expf(r[m] - mx); den += r[m]; }
    float inv = 1.f / den;
    for (int m = 0; m < 12; m++) {
        float av = adj[n * 12 + m] + r[m] * inv;
        g_A[0 * 144 + n * 12 + m] = a1[n * 12 + m] * av;
        g_A[1 * 144 + n * 12 + m] = a2[n * 12 + m] * av;
        g_A[2 * 144 + n * 12 + m] = a3[n * 12 + m] * av;
        g_A[3 * 144 + n * 12 + m] = a4[n * 12 + m] * av;
    }
}

// ---- packed f32x2 helpers -------------------------------------------------
__device__ __forceinline__ unsigned long long f2pack(float x, float y)
{
    unsigned long long r;
    asm("mov.b64 %0, {%1, %2};" : "=l"(r) : "f"(x), "f"(y));
    return r;
}
__device__ __forceinline__ void f2fma(unsigned long long& d, unsigned long long a,
                                      unsigned long long b)
{
    asm("fma.rn.f32x2 %0, %1, %2, %0;" : "+l"(d) : "l"(a), "l"(b));
}
__device__ __forceinline__ float2 f2unp(unsigned long long v)
{
    float2 r;
    asm("mov.b64 {%0, %1}, %2;" : "=f"(r.x), "=f"(r.y) : "l"(v));
    return r;
}

// ---- one GCN layer for a 2-batch tile -------------------------------------
// in  : SMEM, row-major [rows][K]  (rows = 2*12, row = bt*12 + node)
// out : SMEM, row-major [rows][O]  (unless FINAL -> global)
// Each thread computes full columns c of S = H @ W for its assigned rows,
// accumulating in f32x2 pairs over consecutive K (broadcast H operand is a
// single LDS.64; no per-FMA packing MOVs).
// Node mixing (out[n] = sum_m A[n][m]*S[m]) happens in registers.
template <int K, int O, bool FINAL>
__device__ __forceinline__ void gc_layer(const float* __restrict__ in,
                                         float* __restrict__ out,
                                         const float* __restrict__ W,
                                         const float* __restrict__ bias,
                                         const float* __restrict__ A,
                                         float* __restrict__ gout,
                                         long long b0)
{
    const int tid = threadIdx.x;
    constexpr bool BOTH = (O >= 256);       // thread covers both batches
    constexpr int R = BOTH ? 24 : 12;       // rows accumulated per thread
    constexpr int CSTRIDE = BOTH ? 256 : 128;
    const int bt = BOTH ? 0 : (tid >> 7);
    const int lane = BOTH ? tid : (tid & 127);
    const int rb = BOTH ? 0 : bt * 12;

    for (int c = lane; c < O; c += CSTRIDE) {
        unsigned long long acc[R];
#pragma unroll
        for (int r = 0; r < R; r++) acc[r] = 0ull;

#pragma unroll 1
        for (int f = 0; f < K; f += 4) {
            const float* wp = W + f * O + c;
            unsigned long long wA = f2pack(__ldg(wp), __ldg(wp + O));
            unsigned long long wB = f2pack(__ldg(wp + 2 * O), __ldg(wp + 3 * O));
            const float* ip = in + rb * K + f;
#pragma unroll
            for (int r = 0; r < R; ++r) {
                unsigned long long hA = *(const unsigned long long*)(ip + r * K);
                unsigned long long hB = *(const unsigned long long*)(ip + r * K + 2);
                f2fma(acc[r], hA, wA);
                f2fma(acc[r], hB, wB);
            }
        }

        float S[R];
#pragma unroll
        for (int r = 0; r < R; r++) {
            float2 t = f2unp(acc[r]);
            S[r] = t.x + t.y;
        }

        float bv = __ldg(bias + c);
        constexpr int NBT = BOTH ? 2 : 1;
#pragma unroll
        for (int q = 0; q < NBT; ++q) {
            const float* Sv = S + q * 12;
            const int obt = BOTH ? q : bt;
#pragma unroll
            for (int n = 0; n < 12; ++n) {
                float v = 0.f;
#pragma unroll
                for (int m = 0; m < 12; ++m) v = fmaf(A[n * 12 + m], Sv[m], v);
                v = fmaxf(v + bv, 0.f);
                if (FINAL)
                    gout[((b0 + obt) * 12 + n) * 40 + c] = v;
                else
                    out[(obt * 12 + n) * O + c] = v;
            }
        }
    }
}

// SMEM: buf0 (2*12*256 = 6144 floats) | buf1 (2*12*512 = 12288) | A (576)
#define SMEM_FLOATS (6144 + 12288 + 576)

__global__ __launch_bounds__(256) void gcn_main(
    const float* __restrict__ x,
    const float* __restrict__ W1, const float* __restrict__ b1,
    const float* __restrict__ W2, const float* __restrict__ b2,
    const float* __restrict__ W3, const float* __restrict__ b3,
    const float* __restrict__ W4, const float* __restrict__ b4,
    float* __restrict__ out)
{
    extern __shared__ float sm[];
    float* buf0 = sm;                    // stride-256 buffer (x, h2)
    float* buf1 = sm + 6144;             // stride-512 buffer (h1) / stride-128 (h3)
    float* Ash  = sm + 6144 + 12288;     // 4 x 144 mixing matrices

    const int tid = threadIdx.x;
    const long long b0 = (long long)blockIdx.x * 2;

    // FIX: proper strided load of all 576 A-table floats with 256 threads
    for (int i = tid; i < 576; i += 256) Ash[i] = g_A[i];

    // load x tile: 2 batches * 12 * 256 floats = 1536 float4
    const float4* xs = (const float4*)(x + b0 * (NNODE * 256));
    float4* dst = (float4*)buf0;
    for (int i = tid; i < 1536; i += 256) dst[i] = xs[i];
    __syncthreads();

    gc_layer<256, 512, false>(buf0, buf1, W1, b1, Ash + 0,   nullptr, b0);
    __syncthreads();
    gc_layer<512, 256, false>(buf1, buf0, W2, b2, Ash + 144, nullptr, b0);
    __syncthreads();
    gc_layer<256, 128, false>(buf0, buf1, W3, b3, Ash + 288, nullptr, b0);
    __syncthreads();
    gc_layer<128, 40, true>(buf1, nullptr, W4, b4, Ash + 432, out, b0);
}

extern "C" void kernel_launch(void* const* d_in, const int* in_sizes, int n_in,
                              void* d_out, int out_size)
{
    const float* x    = (const float*)d_in[0];
    const float* adj  = (const float*)d_in[1];
    const float* nv1  = (const float*)d_in[2];
    const float* nv2  = (const float*)d_in[3];
    const float* W1   = (const float*)d_in[4];
    const float* att1 = (const float*)d_in[5];
    const float* b1   = (const float*)d_in[6];
    const float* W2   = (const float*)d_in[7];
    const float* att2 = (const float*)d_in[8];
    const float* b2   = (const float*)d_in[9];
    const float* W3   = (const float*)d_in[10];
    const float* att3 = (const float*)d_in[11];
    const float* b3   = (const float*)d_in[12];
    const float* W4   = (const float*)d_in[13];
    const float* att4 = (const float*)d_in[14];
    const float* b4   = (const float*)d_in[15];
    float* out = (float*)d_out;

    precompute_kernel<<<1, 32>>>(adj, nv1, nv2, att1, att2, att3, att4);

    const size_t smem = SMEM_FLOATS * sizeof(float);
    cudaFuncSetAttribute(gcn_main, cudaFuncAttributeMaxDynamicSharedMemorySize,
                         (int)smem);
    gcn_main<<<NB_TOTAL / 2, 256, smem>>>(x, W1, b1, W2, b2, W3, b3, W4, b4, out);
}

// round 4
// speedup vs baseline: 1.4703x; 1.4703x over previous
#include <cuda_runtime.h>
#include <cuda_bf16.h>

// ---------------------------------------------------------------------------
// GCN_33114197852819 : 4-layer GCN, B=65536, N=12, feats 256->512->256->128->40
// Round 3: register-blocked f32x2 kernel. Each thread: 6 rows x NC cols.
// LDS:FMA2 = 1:4 (was 1:1) -> FMA-pipe bound. Node mixing via shfl.xor(16).
// W pre-packed into float4 quads (4 consecutive K per column) by prep kernel.
// ---------------------------------------------------------------------------

#define NB_TOTAL 65536

typedef unsigned long long ull;

// Packed W quads: L1 [64][512] | L2 [128][256] | L3 [64][128] | L4 [32][64 pad]
#define WQ_L1 0
#define WQ_L2 32768
#define WQ_L3 65536
#define WQ_L4 73728
__device__ float4 g_Wq[75776];
__device__ float g_A[576];       // 4 x 12 x 12 mixing matrices
__device__ float g_b4p[64];      // padded layer-4 bias

__global__ void precompute_A(const float* __restrict__ adj,
                             const float* __restrict__ nv1,
                             const float* __restrict__ nv2,
                             const float* __restrict__ a1,
                             const float* __restrict__ a2,
                             const float* __restrict__ a3,
                             const float* __restrict__ a4,
                             const float* __restrict__ b4)
{
    int n = threadIdx.x;
    if (n < 64) g_b4p[n] = (n < 40) ? b4[n] : 0.f;
    if (n >= 12) return;
    float r[12];
    float mx = -1e30f;
    for (int m = 0; m < 12; m++) {
        float s = 0.f;
        for (int k = 0; k < 10; k++) s += nv1[n * 10 + k] * nv2[k * 12 + m];
        s = fmaxf(s, 0.f);
        r[m] = s;
        mx = fmaxf(mx, s);
    }
    float den = 0.f;
    for (int m = 0; m < 12; m++) { r[m] = expf(r[m] - mx); den += r[m]; }
    float inv = 1.f / den;
    for (int m = 0; m < 12; m++) {
        float av = adj[n * 12 + m] + r[m] * inv;
        g_A[0 * 144 + n * 12 + m] = a1[n * 12 + m] * av;
        g_A[1 * 144 + n * 12 + m] = a2[n * 12 + m] * av;
        g_A[2 * 144 + n * 12 + m] = a3[n * 12 + m] * av;
        g_A[3 * 144 + n * 12 + m] = a4[n * 12 + m] * av;
    }
}

// Pack W[K][O] row-major -> quads q[k4][c] = (W[4k4][c],W[4k4+1][c],W[4k4+2][c],W[4k4+3][c])
__global__ void pack_W(const float* __restrict__ W, int K, int O, int Opad,
                       int dstOff)
{
    int idx = blockIdx.x * blockDim.x + threadIdx.x;
    int total = (K / 4) * Opad;
    if (idx >= total) return;
    int k4 = idx / Opad;
    int c = idx % Opad;
    float4 q = make_float4(0.f, 0.f, 0.f, 0.f);
    if (c < O) {
        q.x = W[(4 * k4 + 0) * O + c];
        q.y = W[(4 * k4 + 1) * O + c];
        q.z = W[(4 * k4 + 2) * O + c];
        q.w = W[(4 * k4 + 3) * O + c];
    }
    g_Wq[dstOff + idx] = q;
}

// ---- packed f32x2 helpers -------------------------------------------------
__device__ __forceinline__ ull f2pack(float x, float y)
{
    ull r;
    asm("mov.b64 %0, {%1, %2};" : "=l"(r) : "f"(x), "f"(y));
    return r;
}
__device__ __forceinline__ void f2fma(ull& d, ull a, ull b)
{
    asm("fma.rn.f32x2 %0, %1, %2, %0;" : "+l"(d) : "l"(a), "l"(b));
}
__device__ __forceinline__ float f2sum(ull v)
{
    float x, y;
    asm("mov.b64 {%0, %1}, %2;" : "=f"(x), "=f"(y) : "l"(v));
    return x + y;
}

// ---- one GCN layer --------------------------------------------------------
// in : SMEM [24 rows][K+2 stride], row = bt*12 + node
// Wq : packed quads [K/4][Opad]
// Thread (bt, rh, cg): rows rh*6..rh*6+5 of batch bt, cols c = coff+cg+64*j.
// Mixing: partials for all 12 output nodes, halves combined via shfl.xor(16).
template <int K, int O, int NC, int Opad, bool FINAL>
__device__ __forceinline__ void layer(const float* __restrict__ in,
                                      float* __restrict__ outbuf,
                                      const float4* __restrict__ Wq,
                                      const float* __restrict__ bias,
                                      const float* __restrict__ A,
                                      float* __restrict__ gout,
                                      long long b0, int coff,
                                      int cg, int rh, int bt)
{
    constexpr int IS = K + 2;   // input stride
    const float* hrow = in + (bt * 12 + rh * 6) * IS;
    const float4* wp = Wq + coff + cg;

    ull acc[6][NC];
#pragma unroll
    for (int r = 0; r < 6; r++)
#pragma unroll
        for (int j = 0; j < NC; j++) acc[r][j] = 0ull;

#pragma unroll 2
    for (int k4 = 0; k4 < K / 4; k4++) {
        ull wA[NC], wB[NC];
#pragma unroll
        for (int j = 0; j < NC; j++) {
            float4 w = __ldg(wp + k4 * Opad + 64 * j);
            wA[j] = f2pack(w.x, w.y);
            wB[j] = f2pack(w.z, w.w);
        }
        const float* hp = hrow + 4 * k4;
#pragma unroll
        for (int r = 0; r < 6; r++) {
            ull hA = *(const ull*)(hp + r * IS);
            ull hB = *(const ull*)(hp + r * IS + 2);
#pragma unroll
            for (int j = 0; j < NC; j++) {
                f2fma(acc[r][j], hA, wA[j]);
                f2fma(acc[r][j], hB, wB[j]);
            }
        }
    }

    float S[6][NC];
#pragma unroll
    for (int r = 0; r < 6; r++)
#pragma unroll
        for (int j = 0; j < NC; j++) S[r][j] = f2sum(acc[r][j]);

    // partial mixing: contributions of my 6 m-rows to all 12 output nodes
    float pLo[6][NC], pHi[6][NC];
#pragma unroll
    for (int n = 0; n < 6; n++)
#pragma unroll
        for (int j = 0; j < NC; j++) { pLo[n][j] = 0.f; pHi[n][j] = 0.f; }

    const float* Am = A + rh * 6;   // A[n*12 + rh*6 + i]
#pragma unroll
    for (int i = 0; i < 6; i++) {
#pragma unroll
        for (int n = 0; n < 6; n++) {
            float aLo = Am[n * 12 + i];
            float aHi = Am[(n + 6) * 12 + i];
#pragma unroll
            for (int j = 0; j < NC; j++) {
                pLo[n][j] = fmaf(aLo, S[i][j], pLo[n][j]);
                pHi[n][j] = fmaf(aHi, S[i][j], pHi[n][j]);
            }
        }
    }

    float bj[NC];
#pragma unroll
    for (int j = 0; j < NC; j++) bj[j] = __ldg(bias + coff + cg + 64 * j);

#pragma unroll
    for (int n = 0; n < 6; n++) {
#pragma unroll
        for (int j = 0; j < NC; j++) {
            float send = rh ? pLo[n][j] : pHi[n][j];
            float keep = rh ? pHi[n][j] : pLo[n][j];
            float tot = keep + __shfl_xor_sync(0xffffffffu, send, 16);
            float v = fmaxf(tot + bj[j], 0.f);
            int c = coff + cg + 64 * j;
            int node = rh * 6 + n;
            if (FINAL) {
                if (c < 40) gout[((b0 + bt) * 12 + node) * 40 + c] = v;
            } else {
                outbuf[(bt * 12 + node) * (O + 2) + c] = v;
            }
        }
    }
}

// SMEM: bufA 24*514 = 12336 | bufB 24*258 = 6192 | A 576  -> 19104 floats
#define SMEM_FLOATS (12336 + 6192 + 576)

__global__ __launch_bounds__(256, 2) void gcn_main(
    const float* __restrict__ x,
    const float* __restrict__ b1, const float* __restrict__ b2,
    const float* __restrict__ b3,
    float* __restrict__ out)
{
    extern __shared__ float sm[];
    float* bufA = sm;                 // stride 514 (h1); reused stride 130 (h3)
    float* bufB = sm + 12336;         // stride 258 (x, h2)
    float* Ash  = sm + 12336 + 6192;

    const int tid = threadIdx.x;
    const long long b0 = (long long)blockIdx.x * 2;

    const int cg = (tid & 15) | (((tid >> 5) & 3) << 4);  // 0..63
    const int rh = (tid >> 4) & 1;                        // row half (in-warp)
    const int bt = tid >> 7;                              // batch within tile

    for (int i = tid; i < 576; i += 256) Ash[i] = g_A[i];

    // load x tile: 24 rows x 256 cols into bufB (stride 258), as float2
    {
        const float2* xs = (const float2*)(x + b0 * (12 * 256));
        for (int i = tid; i < 3072; i += 256) {
            int r = i >> 7;
            int cp = i & 127;
            *(float2*)(bufB + r * 258 + 2 * cp) = xs[(size_t)r * 128 + cp];
        }
    }
    __syncthreads();

    // L1: K=256 O=512, two column iterations of 256
    layer<256, 512, 4, 512, false>(bufB, bufA, g_Wq + WQ_L1, b1, Ash + 0,
                                   nullptr, b0, 0, cg, rh, bt);
    layer<256, 512, 4, 512, false>(bufB, bufA, g_Wq + WQ_L1, b1, Ash + 0,
                                   nullptr, b0, 256, cg, rh, bt);
    __syncthreads();   // bufA (h1) complete

    // L2: K=512 O=256 ; epilogue overwrites bufB -> sync inside via 2 phases
    {
        // K-loop reads bufA, epilogue writes bufB (x no longer needed, but
        // ensure all K-loop reads of bufA done before... bufA untouched; bufB
        // overwrite is safe only after all threads stop reading bufB -- bufB
        // was last read in L1 (already synced).  So direct call is fine.
        layer<512, 256, 4, 256, false>(bufA, bufB, g_Wq + WQ_L2, b2, Ash + 144,
                                       nullptr, b0, 0, cg, rh, bt);
    }
    __syncthreads();   // bufB (h2) complete

    // L3: K=256 O=128, NC=2 ; epilogue writes into bufA region (stride 130)
    layer<256, 128, 2, 128, false>(bufB, bufA, g_Wq + WQ_L3, b3, Ash + 288,
                                   nullptr, b0, 0, cg, rh, bt);
    __syncthreads();   // bufA (h3, stride 130) complete

    // L4: K=128 O=40 (padded 64), NC=1, final -> global
    layer<128, 40, 1, 64, true>(bufA, nullptr, g_Wq + WQ_L4, g_b4p, Ash + 432,
                                out, b0, 0, cg, rh, bt);
}

extern "C" void kernel_launch(void* const* d_in, const int* in_sizes, int n_in,
                              void* d_out, int out_size)
{
    const float* x    = (const float*)d_in[0];
    const float* adj  = (const float*)d_in[1];
    const float* nv1  = (const float*)d_in[2];
    const float* nv2  = (const float*)d_in[3];
    const float* W1   = (const float*)d_in[4];
    const float* att1 = (const float*)d_in[5];
    const float* b1   = (const float*)d_in[6];
    const float* W2   = (const float*)d_in[7];
    const float* att2 = (const float*)d_in[8];
    const float* b2   = (const float*)d_in[9];
    const float* W3   = (const float*)d_in[10];
    const float* att3 = (const float*)d_in[11];
    const float* b3   = (const float*)d_in[12];
    const float* W4   = (const float*)d_in[13];
    const float* att4 = (const float*)d_in[14];
    const float* b4   = (const float*)d_in[15];
    float* out = (float*)d_out;

    precompute_A<<<1, 64>>>(adj, nv1, nv2, att1, att2, att3, att4, b4);
    pack_W<<<(64 * 512 + 255) / 256, 256>>>(W1, 256, 512, 512, WQ_L1);
    pack_W<<<(128 * 256 + 255) / 256, 256>>>(W2, 512, 256, 256, WQ_L2);
    pack_W<<<(64 * 128 + 255) / 256, 256>>>(W3, 256, 128, 128, WQ_L3);
    pack_W<<<(32 * 64 + 255) / 256, 256>>>(W4, 128, 40, 64, WQ_L4);

    const size_t smem = SMEM_FLOATS * sizeof(float);
    cudaFuncSetAttribute(gcn_main, cudaFuncAttributeMaxDynamicSharedMemorySize,
                         (int)smem);
    gcn_main<<<NB_TOTAL / 2, 256, smem>>>(x, b1, b2, b3, out);
}

// round 5
// speedup vs baseline: 1.4714x; 1.0008x over previous
#include <cuda_runtime.h>
#include <cuda_bf16.h>

// ---------------------------------------------------------------------------
// GCN_33114197852819 : 4-layer GCN, B=65536, N=12, feats 256->512->256->128->40
// Round 3: register-blocked f32x2 kernel. Each thread: 6 rows x NC cols.
// LDS:FMA2 = 1:4 (was 1:1) -> FMA-pipe bound. Node mixing via shfl.xor(16).
// W pre-packed into float4 quads (4 consecutive K per column) by prep kernel.
// ---------------------------------------------------------------------------

#define NB_TOTAL 65536

typedef unsigned long long ull;

// Packed W quads: L1 [64][512] | L2 [128][256] | L3 [64][128] | L4 [32][64 pad]
#define WQ_L1 0
#define WQ_L2 32768
#define WQ_L3 65536
#define WQ_L4 73728
__device__ float4 g_Wq[75776];
__device__ float g_A[576];       // 4 x 12 x 12 mixing matrices
__device__ float g_b4p[64];      // padded layer-4 bias

__global__ void precompute_A(const float* __restrict__ adj,
                             const float* __restrict__ nv1,
                             const float* __restrict__ nv2,
                             const float* __restrict__ a1,
                             const float* __restrict__ a2,
                             const float* __restrict__ a3,
                             const float* __restrict__ a4,
                             const float* __restrict__ b4)
{
    int n = threadIdx.x;
    if (n < 64) g_b4p[n] = (n < 40) ? b4[n] : 0.f;
    if (n >= 12) return;
    float r[12];
    float mx = -1e30f;
    for (int m = 0; m < 12; m++) {
        float s = 0.f;
        for (int k = 0; k < 10; k++) s += nv1[n * 10 + k] * nv2[k * 12 + m];
        s = fmaxf(s, 0.f);
        r[m] = s;
        mx = fmaxf(mx, s);
    }
    float den = 0.f;
    for (int m = 0; m < 12; m++) { r[m] = expf(r[m] - mx); den += r[m]; }
    float inv = 1.f / den;
    for (int m = 0; m < 12; m++) {
        float av = adj[n * 12 + m] + r[m] * inv;
        g_A[0 * 144 + n * 12 + m] = a1[n * 12 + m] * av;
        g_A[1 * 144 + n * 12 + m] = a2[n * 12 + m] * av;
        g_A[2 * 144 + n * 12 + m] = a3[n * 12 + m] * av;
        g_A[3 * 144 + n * 12 + m] = a4[n * 12 + m] * av;
    }
}

// Pack W[K][O] row-major -> quads q[k4][c] = (W[4k4][c],W[4k4+1][c],W[4k4+2][c],W[4k4+3][c])
__global__ void pack_W(const float* __restrict__ W, int K, int O, int Opad,
                       int dstOff)
{
    int idx = blockIdx.x * blockDim.x + threadIdx.x;
    int total = (K / 4) * Opad;
    if (idx >= total) return;
    int k4 = idx / Opad;
    int c = idx % Opad;
    float4 q = make_float4(0.f, 0.f, 0.f, 0.f);
    if (c < O) {
        q.x = W[(4 * k4 + 0) * O + c];
        q.y = W[(4 * k4 + 1) * O + c];
        q.z = W[(4 * k4 + 2) * O + c];
        q.w = W[(4 * k4 + 3) * O + c];
    }
    g_Wq[dstOff + idx] = q;
}

// ---- packed f32x2 helpers -------------------------------------------------
__device__ __forceinline__ ull f2pack(float x, float y)
{
    ull r;
    asm("mov.b64 %0, {%1, %2};" : "=l"(r) : "f"(x), "f"(y));
    return r;
}
__device__ __forceinline__ void f2fma(ull& d, ull a, ull b)
{
    asm("fma.rn.f32x2 %0, %1, %2, %0;" : "+l"(d) : "l"(a), "l"(b));
}
__device__ __forceinline__ float f2sum(ull v)
{
    float x, y;
    asm("mov.b64 {%0, %1}, %2;" : "=f"(x), "=f"(y) : "l"(v));
    return x + y;
}

// ---- one GCN layer --------------------------------------------------------
// in : SMEM [24 rows][K+2 stride], row = bt*12 + node
// Wq : packed quads [K/4][Opad]
// Thread (bt, rh, cg): rows rh*6..rh*6+5 of batch bt, cols c = coff+cg+64*j.
// Mixing: partials for all 12 output nodes, halves combined via shfl.xor(16).
template <int K, int O, int NC, int Opad, bool FINAL>
__device__ __forceinline__ void layer(const float* __restrict__ in,
                                      float* __restrict__ outbuf,
                                      const float4* __restrict__ Wq,
                                      const float* __restrict__ bias,
                                      const float* __restrict__ A,
                                      float* __restrict__ gout,
                                      long long b0, int coff,
                                      int cg, int rh, int bt)
{
    constexpr int IS = K + 2;   // input stride
    const float* hrow = in + (bt * 12 + rh * 6) * IS;
    const float4* wp = Wq + coff + cg;

    ull acc[6][NC];
#pragma unroll
    for (int r = 0; r < 6; r++)
#pragma unroll
        for (int j = 0; j < NC; j++) acc[r][j] = 0ull;

#pragma unroll 2
    for (int k4 = 0; k4 < K / 4; k4++) {
        ull wA[NC], wB[NC];
#pragma unroll
        for (int j = 0; j < NC; j++) {
            float4 w = __ldg(wp + k4 * Opad + 64 * j);
            wA[j] = f2pack(w.x, w.y);
            wB[j] = f2pack(w.z, w.w);
        }
        const float* hp = hrow + 4 * k4;
#pragma unroll
        for (int r = 0; r < 6; r++) {
            ull hA = *(const ull*)(hp + r * IS);
            ull hB = *(const ull*)(hp + r * IS + 2);
#pragma unroll
            for (int j = 0; j < NC; j++) {
                f2fma(acc[r][j], hA, wA[j]);
                f2fma(acc[r][j], hB, wB[j]);
            }
        }
    }

    float S[6][NC];
#pragma unroll
    for (int r = 0; r < 6; r++)
#pragma unroll
        for (int j = 0; j < NC; j++) S[r][j] = f2sum(acc[r][j]);

    // partial mixing: contributions of my 6 m-rows to all 12 output nodes
    float pLo[6][NC], pHi[6][NC];
#pragma unroll
    for (int n = 0; n < 6; n++)
#pragma unroll
        for (int j = 0; j < NC; j++) { pLo[n][j] = 0.f; pHi[n][j] = 0.f; }

    const float* Am = A + rh * 6;   // A[n*12 + rh*6 + i]
#pragma unroll
    for (int i = 0; i < 6; i++) {
#pragma unroll
        for (int n = 0; n < 6; n++) {
            float aLo = Am[n * 12 + i];
            float aHi = Am[(n + 6) * 12 + i];
#pragma unroll
            for (int j = 0; j < NC; j++) {
                pLo[n][j] = fmaf(aLo, S[i][j], pLo[n][j]);
                pHi[n][j] = fmaf(aHi, S[i][j], pHi[n][j]);
            }
        }
    }

    float bj[NC];
#pragma unroll
    for (int j = 0; j < NC; j++) bj[j] = __ldg(bias + coff + cg + 64 * j);

#pragma unroll
    for (int n = 0; n < 6; n++) {
#pragma unroll
        for (int j = 0; j < NC; j++) {
            float send = rh ? pLo[n][j] : pHi[n][j];
            float keep = rh ? pHi[n][j] : pLo[n][j];
            float tot = keep + __shfl_xor_sync(0xffffffffu, send, 16);
            float v = fmaxf(tot + bj[j], 0.f);
            int c = coff + cg + 64 * j;
            int node = rh * 6 + n;
            if (FINAL) {
                if (c < 40) gout[((b0 + bt) * 12 + node) * 40 + c] = v;
            } else {
                outbuf[(bt * 12 + node) * (O + 2) + c] = v;
            }
        }
    }
}

// SMEM: bufA 24*514 = 12336 | bufB 24*258 = 6192 | A 576  -> 19104 floats
#define SMEM_FLOATS (12336 + 6192 + 576)

__global__ __launch_bounds__(256, 2) void gcn_main(
    const float* __restrict__ x,
    const float* __restrict__ b1, const float* __restrict__ b2,
    const float* __restrict__ b3,
    float* __restrict__ out)
{
    extern __shared__ float sm[];
    float* bufA = sm;                 // stride 514 (h1); reused stride 130 (h3)
    float* bufB = sm + 12336;         // stride 258 (x, h2)
    float* Ash  = sm + 12336 + 6192;

    const int tid = threadIdx.x;
    const long long b0 = (long long)blockIdx.x * 2;

    const int cg = (tid & 15) | (((tid >> 5) & 3) << 4);  // 0..63
    const int rh = (tid >> 4) & 1;                        // row half (in-warp)
    const int bt = tid >> 7;                              // batch within tile

    for (int i = tid; i < 576; i += 256) Ash[i] = g_A[i];

    // load x tile: 24 rows x 256 cols into bufB (stride 258), as float2
    {
        const float2* xs = (const float2*)(x + b0 * (12 * 256));
        for (int i = tid; i < 3072; i += 256) {
            int r = i >> 7;
            int cp = i & 127;
            *(float2*)(bufB + r * 258 + 2 * cp) = xs[(size_t)r * 128 + cp];
        }
    }
    __syncthreads();

    // L1: K=256 O=512, two column iterations of 256
    layer<256, 512, 4, 512, false>(bufB, bufA, g_Wq + WQ_L1, b1, Ash + 0,
                                   nullptr, b0, 0, cg, rh, bt);
    layer<256, 512, 4, 512, false>(bufB, bufA, g_Wq + WQ_L1, b1, Ash + 0,
                                   nullptr, b0, 256, cg, rh, bt);
    __syncthreads();   // bufA (h1) complete

    // L2: K=512 O=256 ; epilogue overwrites bufB -> sync inside via 2 phases
    {
        // K-loop reads bufA, epilogue writes bufB (x no longer needed, but
        // ensure all K-loop reads of bufA done before... bufA untouched; bufB
        // overwrite is safe only after all threads stop reading bufB -- bufB
        // was last read in L1 (already synced).  So direct call is fine.
        layer<512, 256, 4, 256, false>(bufA, bufB, g_Wq + WQ_L2, b2, Ash + 144,
                                       nullptr, b0, 0, cg, rh, bt);
    }
    __syncthreads();   // bufB (h2) complete

    // L3: K=256 O=128, NC=2 ; epilogue writes into bufA region (stride 130)
    layer<256, 128, 2, 128, false>(bufB, bufA, g_Wq + WQ_L3, b3, Ash + 288,
                                   nullptr, b0, 0, cg, rh, bt);
    __syncthreads();   // bufA (h3, stride 130) complete

    // L4: K=128 O=40 (padded 64), NC=1, final -> global
    layer<128, 40, 1, 64, true>(bufA, nullptr, g_Wq + WQ_L4, g_b4p, Ash + 432,
                                out, b0, 0, cg, rh, bt);
}

extern "C" void kernel_launch(void* const* d_in, const int* in_sizes, int n_in,
                              void* d_out, int out_size)
{
    const float* x    = (const float*)d_in[0];
    const float* adj  = (const float*)d_in[1];
    const float* nv1  = (const float*)d_in[2];
    const float* nv2  = (const float*)d_in[3];
    const float* W1   = (const float*)d_in[4];
    const float* att1 = (const float*)d_in[5];
    const float* b1   = (const float*)d_in[6];
    const float* W2   = (const float*)d_in[7];
    const float* att2 = (const float*)d_in[8];
    const float* b2   = (const float*)d_in[9];
    const float* W3   = (const float*)d_in[10];
    const float* att3 = (const float*)d_in[11];
    const float* b3   = (const float*)d_in[12];
    const float* W4   = (const float*)d_in[13];
    const float* att4 = (const float*)d_in[14];
    const float* b4   = (const float*)d_in[15];
    float* out = (float*)d_out;

    precompute_A<<<1, 64>>>(adj, nv1, nv2, att1, att2, att3, att4, b4);
    pack_W<<<(64 * 512 + 255) / 256, 256>>>(W1, 256, 512, 512, WQ_L1);
    pack_W<<<(128 * 256 + 255) / 256, 256>>>(W2, 512, 256, 256, WQ_L2);
    pack_W<<<(64 * 128 + 255) / 256, 256>>>(W3, 256, 128, 128, WQ_L3);
    pack_W<<<(32 * 64 + 255) / 256, 256>>>(W4, 128, 40, 64, WQ_L4);

    const size_t smem = SMEM_FLOATS * sizeof(float);
    cudaFuncSetAttribute(gcn_main, cudaFuncAttributeMaxDynamicSharedMemorySize,
                         (int)smem);
    gcn_main<<<NB_TOTAL / 2, 256, smem>>>(x, b1, b2, b3, out);
}

// round 6
// speedup vs baseline: 1.4726x; 1.0008x over previous
#include <cuda_runtime.h>
#include <cuda_bf16.h>

// ---------------------------------------------------------------------------
// GCN_33114197852819 : 4-layer GCN, B=65536, N=12, feats 256->512->256->128->40
// Round 3: register-blocked f32x2 kernel. Each thread: 6 rows x NC cols.
// LDS:FMA2 = 1:4 (was 1:1) -> FMA-pipe bound. Node mixing via shfl.xor(16).
// W pre-packed into float4 quads (4 consecutive K per column) by prep kernel.
// ---------------------------------------------------------------------------

#define NB_TOTAL 65536

typedef unsigned long long ull;

// Packed W quads: L1 [64][512] | L2 [128][256] | L3 [64][128] | L4 [32][64 pad]
#define WQ_L1 0
#define WQ_L2 32768
#define WQ_L3 65536
#define WQ_L4 73728
__device__ float4 g_Wq[75776];
__device__ float g_A[576];       // 4 x 12 x 12 mixing matrices
__device__ float g_b4p[64];      // padded layer-4 bias

__global__ void precompute_A(const float* __restrict__ adj,
                             const float* __restrict__ nv1,
                             const float* __restrict__ nv2,
                             const float* __restrict__ a1,
                             const float* __restrict__ a2,
                             const float* __restrict__ a3,
                             const float* __restrict__ a4,
                             const float* __restrict__ b4)
{
    int n = threadIdx.x;
    if (n < 64) g_b4p[n] = (n < 40) ? b4[n] : 0.f;
    if (n >= 12) return;
    float r[12];
    float mx = -1e30f;
    for (int m = 0; m < 12; m++) {
        float s = 0.f;
        for (int k = 0; k < 10; k++) s += nv1[n * 10 + k] * nv2[k * 12 + m];
        s = fmaxf(s, 0.f);
        r[m] = s;
        mx = fmaxf(mx, s);
    }
    float den = 0.f;
    for (int m = 0; m < 12; m++) { r[m] = expf(r[m] - mx); den += r[m]; }
    float inv = 1.f / den;
    for (int m = 0; m < 12; m++) {
        float av = adj[n * 12 + m] + r[m] * inv;
        g_A[0 * 144 + n * 12 + m] = a1[n * 12 + m] * av;
        g_A[1 * 144 + n * 12 + m] = a2[n * 12 + m] * av;
        g_A[2 * 144 + n * 12 + m] = a3[n * 12 + m] * av;
        g_A[3 * 144 + n * 12 + m] = a4[n * 12 + m] * av;
    }
}

// Pack W[K][O] row-major -> quads q[k4][c] = (W[4k4][c],W[4k4+1][c],W[4k4+2][c],W[4k4+3][c])
__global__ void pack_W(const float* __restrict__ W, int K, int O, int Opad,
                       int dstOff)
{
    int idx = blockIdx.x * blockDim.x + threadIdx.x;
    int total = (K / 4) * Opad;
    if (idx >= total) return;
    int k4 = idx / Opad;
    int c = idx % Opad;
    float4 q = make_float4(0.f, 0.f, 0.f, 0.f);
    if (c < O) {
        q.x = W[(4 * k4 + 0) * O + c];
        q.y = W[(4 * k4 + 1) * O + c];
        q.z = W[(4 * k4 + 2) * O + c];
        q.w = W[(4 * k4 + 3) * O + c];
    }
    g_Wq[dstOff + idx] = q;
}

// ---- packed f32x2 helpers -------------------------------------------------
__device__ __forceinline__ ull f2pack(float x, float y)
{
    ull r;
    asm("mov.b64 %0, {%1, %2};" : "=l"(r) : "f"(x), "f"(y));
    return r;
}
__device__ __forceinline__ void f2fma(ull& d, ull a, ull b)
{
    asm("fma.rn.f32x2 %0, %1, %2, %0;" : "+l"(d) : "l"(a), "l"(b));
}
__device__ __forceinline__ float f2sum(ull v)
{
    float x, y;
    asm("mov.b64 {%0, %1}, %2;" : "=f"(x), "=f"(y) : "l"(v));
    return x + y;
}

// ---- one GCN layer --------------------------------------------------------
// in : SMEM [24 rows][K+2 stride], row = bt*12 + node
// Wq : packed quads [K/4][Opad]
// Thread (bt, rh, cg): rows rh*6..rh*6+5 of batch bt, cols c = coff+cg+64*j.
// Mixing: partials for all 12 output nodes, halves combined via shfl.xor(16).
template <int K, int O, int NC, int Opad, bool FINAL>
__device__ __forceinline__ void layer(const float* __restrict__ in,
                                      float* __restrict__ outbuf,
                                      const float4* __restrict__ Wq,
                                      const float* __restrict__ bias,
                                      const float* __restrict__ A,
                                      float* __restrict__ gout,
                                      long long b0, int coff,
                                      int cg, int rh, int bt)
{
    constexpr int IS = K + 2;   // input stride
    const float* hrow = in + (bt * 12 + rh * 6) * IS;
    const float4* wp = Wq + coff + cg;

    ull acc[6][NC];
#pragma unroll
    for (int r = 0; r < 6; r++)
#pragma unroll
        for (int j = 0; j < NC; j++) acc[r][j] = 0ull;

#pragma unroll 2
    for (int k4 = 0; k4 < K / 4; k4++) {
        ull wA[NC], wB[NC];
#pragma unroll
        for (int j = 0; j < NC; j++) {
            float4 w = __ldg(wp + k4 * Opad + 64 * j);
            wA[j] = f2pack(w.x, w.y);
            wB[j] = f2pack(w.z, w.w);
        }
        const float* hp = hrow + 4 * k4;
#pragma unroll
        for (int r = 0; r < 6; r++) {
            ull hA = *(const ull*)(hp + r * IS);
            ull hB = *(const ull*)(hp + r * IS + 2);
#pragma unroll
            for (int j = 0; j < NC; j++) {
                f2fma(acc[r][j], hA, wA[j]);
                f2fma(acc[r][j], hB, wB[j]);
            }
        }
    }

    float S[6][NC];
#pragma unroll
    for (int r = 0; r < 6; r++)
#pragma unroll
        for (int j = 0; j < NC; j++) S[r][j] = f2sum(acc[r][j]);

    // partial mixing: contributions of my 6 m-rows to all 12 output nodes
    float pLo[6][NC], pHi[6][NC];
#pragma unroll
    for (int n = 0; n < 6; n++)
#pragma unroll
        for (int j = 0; j < NC; j++) { pLo[n][j] = 0.f; pHi[n][j] = 0.f; }

    const float* Am = A + rh * 6;   // A[n*12 + rh*6 + i]
#pragma unroll
    for (int i = 0; i < 6; i++) {
#pragma unroll
        for (int n = 0; n < 6; n++) {
            float aLo = Am[n * 12 + i];
            float aHi = Am[(n + 6) * 12 + i];
#pragma unroll
            for (int j = 0; j < NC; j++) {
                pLo[n][j] = fmaf(aLo, S[i][j], pLo[n][j]);
                pHi[n][j] = fmaf(aHi, S[i][j], pHi[n][j]);
            }
        }
    }

    float bj[NC];
#pragma unroll
    for (int j = 0; j < NC; j++) bj[j] = __ldg(bias + coff + cg + 64 * j);

#pragma unroll
    for (int n = 0; n < 6; n++) {
#pragma unroll
        for (int j = 0; j < NC; j++) {
            float send = rh ? pLo[n][j] : pHi[n][j];
            float keep = rh ? pHi[n][j] : pLo[n][j];
            float tot = keep + __shfl_xor_sync(0xffffffffu, send, 16);
            float v = fmaxf(tot + bj[j], 0.f);
            int c = coff + cg + 64 * j;
            int node = rh * 6 + n;
            if (FINAL) {
                if (c < 40) gout[((b0 + bt) * 12 + node) * 40 + c] = v;
            } else {
                outbuf[(bt * 12 + node) * (O + 2) + c] = v;
            }
        }
    }
}

// SMEM: bufA 24*514 = 12336 | bufB 24*258 = 6192 | A 576  -> 19104 floats
#define SMEM_FLOATS (12336 + 6192 + 576)

__global__ __launch_bounds__(256, 2) void gcn_main(
    const float* __restrict__ x,
    const float* __restrict__ b1, const float* __restrict__ b2,
    const float* __restrict__ b3,
    float* __restrict__ out)
{
    extern __shared__ float sm[];
    float* bufA = sm;                 // stride 514 (h1); reused stride 130 (h3)
    float* bufB = sm + 12336;         // stride 258 (x, h2)
    float* Ash  = sm + 12336 + 6192;

    const int tid = threadIdx.x;
    const long long b0 = (long long)blockIdx.x * 2;

    const int cg = (tid & 15) | (((tid >> 5) & 3) << 4);  // 0..63
    const int rh = (tid >> 4) & 1;                        // row half (in-warp)
    const int bt = tid >> 7;                              // batch within tile

    for (int i = tid; i < 576; i += 256) Ash[i] = g_A[i];

    // load x tile: 24 rows x 256 cols into bufB (stride 258), as float2
    {
        const float2* xs = (const float2*)(x + b0 * (12 * 256));
        for (int i = tid; i < 3072; i += 256) {
            int r = i >> 7;
            int cp = i & 127;
            *(float2*)(bufB + r * 258 + 2 * cp) = xs[(size_t)r * 128 + cp];
        }
    }
    __syncthreads();

    // L1: K=256 O=512, two column iterations of 256
    layer<256, 512, 4, 512, false>(bufB, bufA, g_Wq + WQ_L1, b1, Ash + 0,
                                   nullptr, b0, 0, cg, rh, bt);
    layer<256, 512, 4, 512, false>(bufB, bufA, g_Wq + WQ_L1, b1, Ash + 0,
                                   nullptr, b0, 256, cg, rh, bt);
    __syncthreads();   // bufA (h1) complete

    // L2: K=512 O=256 ; epilogue overwrites bufB -> sync inside via 2 phases
    {
        // K-loop reads bufA, epilogue writes bufB (x no longer needed, but
        // ensure all K-loop reads of bufA done before... bufA untouched; bufB
        // overwrite is safe only after all threads stop reading bufB -- bufB
        // was last read in L1 (already synced).  So direct call is fine.
        layer<512, 256, 4, 256, false>(bufA, bufB, g_Wq + WQ_L2, b2, Ash + 144,
                                       nullptr, b0, 0, cg, rh, bt);
    }
    __syncthreads();   // bufB (h2) complete

    // L3: K=256 O=128, NC=2 ; epilogue writes into bufA region (stride 130)
    layer<256, 128, 2, 128, false>(bufB, bufA, g_Wq + WQ_L3, b3, Ash + 288,
                                   nullptr, b0, 0, cg, rh, bt);
    __syncthreads();   // bufA (h3, stride 130) complete

    // L4: K=128 O=40 (padded 64), NC=1, final -> global
    layer<128, 40, 1, 64, true>(bufA, nullptr, g_Wq + WQ_L4, g_b4p, Ash + 432,
                                out, b0, 0, cg, rh, bt);
}

extern "C" void kernel_launch(void* const* d_in, const int* in_sizes, int n_in,
                              void* d_out, int out_size)
{
    const float* x    = (const float*)d_in[0];
    const float* adj  = (const float*)d_in[1];
    const float* nv1  = (const float*)d_in[2];
    const float* nv2  = (const float*)d_in[3];
    const float* W1   = (const float*)d_in[4];
    const float* att1 = (const float*)d_in[5];
    const float* b1   = (const float*)d_in[6];
    const float* W2   = (const float*)d_in[7];
    const float* att2 = (const float*)d_in[8];
    const float* b2   = (const float*)d_in[9];
    const float* W3   = (const float*)d_in[10];
    const float* att3 = (const float*)d_in[11];
    const float* b3   = (const float*)d_in[12];
    const float* W4   = (const float*)d_in[13];
    const float* att4 = (const float*)d_in[14];
    const float* b4   = (const float*)d_in[15];
    float* out = (float*)d_out;

    precompute_A<<<1, 64>>>(adj, nv1, nv2, att1, att2, att3, att4, b4);
    pack_W<<<(64 * 512 + 255) / 256, 256>>>(W1, 256, 512, 512, WQ_L1);
    pack_W<<<(128 * 256 + 255) / 256, 256>>>(W2, 512, 256, 256, WQ_L2);
    pack_W<<<(64 * 128 + 255) / 256, 256>>>(W3, 256, 128, 128, WQ_L3);
    pack_W<<<(32 * 64 + 255) / 256, 256>>>(W4, 128, 40, 64, WQ_L4);

    const size_t smem = SMEM_FLOATS * sizeof(float);
    cudaFuncSetAttribute(gcn_main, cudaFuncAttributeMaxDynamicSharedMemorySize,
                         (int)smem);
    gcn_main<<<NB_TOTAL / 2, 256, smem>>>(x, b1, b2, b3, out);
}

// round 7
// speedup vs baseline: 1.4734x; 1.0005x over previous
#include <cuda_runtime.h>
#include <cuda_bf16.h>

// ---------------------------------------------------------------------------
// GCN_33114197852819 : 4-layer GCN, B=65536, N=12, feats 256->512->256->128->40
// Round 3: register-blocked f32x2 kernel. Each thread: 6 rows x NC cols.
// LDS:FMA2 = 1:4 (was 1:1) -> FMA-pipe bound. Node mixing via shfl.xor(16).
// W pre-packed into float4 quads (4 consecutive K per column) by prep kernel.
// ---------------------------------------------------------------------------

#define NB_TOTAL 65536

typedef unsigned long long ull;

// Packed W quads: L1 [64][512] | L2 [128][256] | L3 [64][128] | L4 [32][64 pad]
#define WQ_L1 0
#define WQ_L2 32768
#define WQ_L3 65536
#define WQ_L4 73728
__device__ float4 g_Wq[75776];
__device__ float g_A[576];       // 4 x 12 x 12 mixing matrices
__device__ float g_b4p[64];      // padded layer-4 bias

__global__ void precompute_A(const float* __restrict__ adj,
                             const float* __restrict__ nv1,
                             const float* __restrict__ nv2,
                             const float* __restrict__ a1,
                             const float* __restrict__ a2,
                             const float* __restrict__ a3,
                             const float* __restrict__ a4,
                             const float* __restrict__ b4)
{
    int n = threadIdx.x;
    if (n < 64) g_b4p[n] = (n < 40) ? b4[n] : 0.f;
    if (n >= 12) return;
    float r[12];
    float mx = -1e30f;
    for (int m = 0; m < 12; m++) {
        float s = 0.f;
        for (int k = 0; k < 10; k++) s += nv1[n * 10 + k] * nv2[k * 12 + m];
        s = fmaxf(s, 0.f);
        r[m] = s;
        mx = fmaxf(mx, s);
    }
    float den = 0.f;
    for (int m = 0; m < 12; m++) { r[m] = expf(r[m] - mx); den += r[m]; }
    float inv = 1.f / den;
    for (int m = 0; m < 12; m++) {
        float av = adj[n * 12 + m] + r[m] * inv;
        g_A[0 * 144 + n * 12 + m] = a1[n * 12 + m] * av;
        g_A[1 * 144 + n * 12 + m] = a2[n * 12 + m] * av;
        g_A[2 * 144 + n * 12 + m] = a3[n * 12 + m] * av;
        g_A[3 * 144 + n * 12 + m] = a4[n * 12 + m] * av;
    }
}

// Pack W[K][O] row-major -> quads q[k4][c] = (W[4k4][c],W[4k4+1][c],W[4k4+2][c],W[4k4+3][c])
__global__ void pack_W(const float* __restrict__ W, int K, int O, int Opad,
                       int dstOff)
{
    int idx = blockIdx.x * blockDim.x + threadIdx.x;
    int total = (K / 4) * Opad;
    if (idx >= total) return;
    int k4 = idx / Opad;
    int c = idx % Opad;
    float4 q = make_float4(0.f, 0.f, 0.f, 0.f);
    if (c < O) {
        q.x = W[(4 * k4 + 0) * O + c];
        q.y = W[(4 * k4 + 1) * O + c];
        q.z = W[(4 * k4 + 2) * O + c];
        q.w = W[(4 * k4 + 3) * O + c];
    }
    g_Wq[dstOff + idx] = q;
}

// ---- packed f32x2 helpers -------------------------------------------------
__device__ __forceinline__ ull f2pack(float x, float y)
{
    ull r;
    asm("mov.b64 %0, {%1, %2};" : "=l"(r) : "f"(x), "f"(y));
    return r;
}
__device__ __forceinline__ void f2fma(ull& d, ull a, ull b)
{
    asm("fma.rn.f32x2 %0, %1, %2, %0;" : "+l"(d) : "l"(a), "l"(b));
}
__device__ __forceinline__ float f2sum(ull v)
{
    float x, y;
    asm("mov.b64 {%0, %1}, %2;" : "=f"(x), "=f"(y) : "l"(v));
    return x + y;
}

// ---- one GCN layer --------------------------------------------------------
// in : SMEM [24 rows][K+2 stride], row = bt*12 + node
// Wq : packed quads [K/4][Opad]
// Thread (bt, rh, cg): rows rh*6..rh*6+5 of batch bt, cols c = coff+cg+64*j.
// Mixing: partials for all 12 output nodes, halves combined via shfl.xor(16).
template <int K, int O, int NC, int Opad, bool FINAL>
__device__ __forceinline__ void layer(const float* __restrict__ in,
                                      float* __restrict__ outbuf,
                                      const float4* __restrict__ Wq,
                                      const float* __restrict__ bias,
                                      const float* __restrict__ A,
                                      float* __restrict__ gout,
                                      long long b0, int coff,
                                      int cg, int rh, int bt)
{
    constexpr int IS = K + 2;   // input stride
    const float* hrow = in + (bt * 12 + rh * 6) * IS;
    const float4* wp = Wq + coff + cg;

    ull acc[6][NC];
#pragma unroll
    for (int r = 0; r < 6; r++)
#pragma unroll
        for (int j = 0; j < NC; j++) acc[r][j] = 0ull;

#pragma unroll 2
    for (int k4 = 0; k4 < K / 4; k4++) {
        ull wA[NC], wB[NC];
#pragma unroll
        for (int j = 0; j < NC; j++) {
            float4 w = __ldg(wp + k4 * Opad + 64 * j);
            wA[j] = f2pack(w.x, w.y);
            wB[j] = f2pack(w.z, w.w);
        }
        const float* hp = hrow + 4 * k4;
#pragma unroll
        for (int r = 0; r < 6; r++) {
            ull hA = *(const ull*)(hp + r * IS);
            ull hB = *(const ull*)(hp + r * IS + 2);
#pragma unroll
            for (int j = 0; j < NC; j++) {
                f2fma(acc[r][j], hA, wA[j]);
                f2fma(acc[r][j], hB, wB[j]);
            }
        }
    }

    float S[6][NC];
#pragma unroll
    for (int r = 0; r < 6; r++)
#pragma unroll
        for (int j = 0; j < NC; j++) S[r][j] = f2sum(acc[r][j]);

    // partial mixing: contributions of my 6 m-rows to all 12 output nodes
    float pLo[6][NC], pHi[6][NC];
#pragma unroll
    for (int n = 0; n < 6; n++)
#pragma unroll
        for (int j = 0; j < NC; j++) { pLo[n][j] = 0.f; pHi[n][j] = 0.f; }

    const float* Am = A + rh * 6;   // A[n*12 + rh*6 + i]
#pragma unroll
    for (int i = 0; i < 6; i++) {
#pragma unroll
        for (int n = 0; n < 6; n++) {
            float aLo = Am[n * 12 + i];
            float aHi = Am[(n + 6) * 12 + i];
#pragma unroll
            for (int j = 0; j < NC; j++) {
                pLo[n][j] = fmaf(aLo, S[i][j], pLo[n][j]);
                pHi[n][j] = fmaf(aHi, S[i][j], pHi[n][j]);
            }
        }
    }

    float bj[NC];
#pragma unroll
    for (int j = 0; j < NC; j++) bj[j] = __ldg(bias + coff + cg + 64 * j);

#pragma unroll
    for (int n = 0; n < 6; n++) {
#pragma unroll
        for (int j = 0; j < NC; j++) {
            float send = rh ? pLo[n][j] : pHi[n][j];
            float keep = rh ? pHi[n][j] : pLo[n][j];
            float tot = keep + __shfl_xor_sync(0xffffffffu, send, 16);
            float v = fmaxf(tot + bj[j], 0.f);
            int c = coff + cg + 64 * j;
            int node = rh * 6 + n;
            if (FINAL) {
                if (c < 40) gout[((b0 + bt) * 12 + node) * 40 + c] = v;
            } else {
                outbuf[(bt * 12 + node) * (O + 2) + c] = v;
            }
        }
    }
}

// SMEM: bufA 24*514 = 12336 | bufB 24*258 = 6192 | A 576  -> 19104 floats
#define SMEM_FLOATS (12336 + 6192 + 576)

__global__ __launch_bounds__(256, 2) void gcn_main(
    const float* __restrict__ x,
    const float* __restrict__ b1, const float* __restrict__ b2,
    const float* __restrict__ b3,
    float* __restrict__ out)
{
    extern __shared__ float sm[];
    float* bufA = sm;                 // stride 514 (h1); reused stride 130 (h3)
    float* bufB = sm + 12336;         // stride 258 (x, h2)
    float* Ash  = sm + 12336 + 6192;

    const int tid = threadIdx.x;
    const long long b0 = (long long)blockIdx.x * 2;

    const int cg = (tid & 15) | (((tid >> 5) & 3) << 4);  // 0..63
    const int rh = (tid >> 4) & 1;                        // row half (in-warp)
    const int bt = tid >> 7;                              // batch within tile

    for (int i = tid; i < 576; i += 256) Ash[i] = g_A[i];

    // load x tile: 24 rows x 256 cols into bufB (stride 258), as float2
    {
        const float2* xs = (const float2*)(x + b0 * (12 * 256));
        for (int i = tid; i < 3072; i += 256) {
            int r = i >> 7;
            int cp = i & 127;
            *(float2*)(bufB + r * 258 + 2 * cp) = xs[(size_t)r * 128 + cp];
        }
    }
    __syncthreads();

    // L1: K=256 O=512, two column iterations of 256
    layer<256, 512, 4, 512, false>(bufB, bufA, g_Wq + WQ_L1, b1, Ash + 0,
                                   nullptr, b0, 0, cg, rh, bt);
    layer<256, 512, 4, 512, false>(bufB, bufA, g_Wq + WQ_L1, b1, Ash + 0,
                                   nullptr, b0, 256, cg, rh, bt);
    __syncthreads();   // bufA (h1) complete

    // L2: K=512 O=256 ; epilogue overwrites bufB -> sync inside via 2 phases
    {
        // K-loop reads bufA, epilogue writes bufB (x no longer needed, but
        // ensure all K-loop reads of bufA done before... bufA untouched; bufB
        // overwrite is safe only after all threads stop reading bufB -- bufB
        // was last read in L1 (already synced).  So direct call is fine.
        layer<512, 256, 4, 256, false>(bufA, bufB, g_Wq + WQ_L2, b2, Ash + 144,
                                       nullptr, b0, 0, cg, rh, bt);
    }
    __syncthreads();   // bufB (h2) complete

    // L3: K=256 O=128, NC=2 ; epilogue writes into bufA region (stride 130)
    layer<256, 128, 2, 128, false>(bufB, bufA, g_Wq + WQ_L3, b3, Ash + 288,
                                   nullptr, b0, 0, cg, rh, bt);
    __syncthreads();   // bufA (h3, stride 130) complete

    // L4: K=128 O=40 (padded 64), NC=1, final -> global
    layer<128, 40, 1, 64, true>(bufA, nullptr, g_Wq + WQ_L4, g_b4p, Ash + 432,
                                out, b0, 0, cg, rh, bt);
}

extern "C" void kernel_launch(void* const* d_in, const int* in_sizes, int n_in,
                              void* d_out, int out_size)
{
    const float* x    = (const float*)d_in[0];
    const float* adj  = (const float*)d_in[1];
    const float* nv1  = (const float*)d_in[2];
    const float* nv2  = (const float*)d_in[3];
    const float* W1   = (const float*)d_in[4];
    const float* att1 = (const float*)d_in[5];
    const float* b1   = (const float*)d_in[6];
    const float* W2   = (const float*)d_in[7];
    const float* att2 = (const float*)d_in[8];
    const float* b2   = (const float*)d_in[9];
    const float* W3   = (const float*)d_in[10];
    const float* att3 = (const float*)d_in[11];
    const float* b3   = (const float*)d_in[12];
    const float* W4   = (const float*)d_in[13];
    const float* att4 = (const float*)d_in[14];
    const float* b4   = (const float*)d_in[15];
    float* out = (float*)d_out;

    precompute_A<<<1, 64>>>(adj, nv1, nv2, att1, att2, att3, att4, b4);
    pack_W<<<(64 * 512 + 255) / 256, 256>>>(W1, 256, 512, 512, WQ_L1);
    pack_W<<<(128 * 256 + 255) / 256, 256>>>(W2, 512, 256, 256, WQ_L2);
    pack_W<<<(64 * 128 + 255) / 256, 256>>>(W3, 256, 128, 128, WQ_L3);
    pack_W<<<(32 * 64 + 255) / 256, 256>>>(W4, 128, 40, 64, WQ_L4);

    const size_t smem = SMEM_FLOATS * sizeof(float);
    cudaFuncSetAttribute(gcn_main, cudaFuncAttributeMaxDynamicSharedMemorySize,
                         (int)smem);
    gcn_main<<<NB_TOTAL / 2, 256, smem>>>(x, b1, b2, b3, out);
}